// round 16
// baseline (speedup 1.0000x reference)
#include <cuda_runtime.h>

#define N_MAT 50000
#define N_EDGE 800000
#define D 64
#define NB_SCAN 196   // ceil(N_MAT/256)
#define NODES_NB 782  // ceil(N_MAT/64)
#define ESC_NB 3125   // N_EDGE/256

// ---------------- scratch (static device memory; no allocations) ----------------
__device__ __align__(16) float g_h[N_MAT * D];
__device__ __align__(16) float g_Y[N_MAT * D];
__device__ float g_d[N_MAT];
__device__ float g_p[N_MAT];
__device__ float g_expself[N_MAT];
__device__ float g_expcross[N_EDGE];
__device__ float g_b[D];
__device__ float g_sum;
__device__ int g_cnt[N_MAT];
__device__ int g_start[N_MAT];
__device__ int g_cur[N_MAT];
__device__ int g_part[NB_SCAN];
__device__ float g_part_self[NODES_NB];
__device__ float g_part_cross[ESC_NB];
__device__ __align__(16) uint4 g_csr[N_EDGE];   // {eid, src, bits(exp), pad}

__device__ __forceinline__ float warp_sum(float v) {
#pragma unroll
    for (int o = 16; o; o >>= 1) v += __shfl_xor_sync(0xffffffffu, v, o);
    return v;
}

// ---- K1: register-tiled h = mat @ W_mat^T + d + self-score
//      + per-block cnt zeroing + block0 computes b (champion version) -----------
__global__ void __launch_bounds__(256) k_nodes(const float* __restrict__ mat,
                                               const float* __restrict__ W_mat,
                                               const float* __restrict__ a_self,
                                               const float* __restrict__ a_cross,
                                               const float* __restrict__ W_op) {
    __shared__ float m[64 * 68];
    __shared__ float wt[64 * 68];
    __shared__ float ac1[64], asc[64];
    __shared__ float s_ex[16];
    int tid = threadIdx.x;
    int rowbase = blockIdx.x * 64;

    if (tid < 64 && rowbase + tid < N_MAT) g_cnt[rowbase + tid] = 0;
    if (blockIdx.x == 0 && tid >= 64 && tid < 128) {
        int jj = tid - 64;
        float bb = 0.f;
#pragma unroll
        for (int c = 0; c < D; c++) bb += a_cross[D + c] * W_op[c * D + jj];
        g_b[jj] = bb;
    }

    for (int e = tid; e < 4096; e += 256)
        wt[(e & 63) * 68 + (e >> 6)] = W_mat[e];
    if (tid < 64) { ac1[tid] = a_cross[tid]; asc[tid] = a_self[tid] + a_self[64 + tid]; }
    const float4* mat4 = (const float4*)mat;
#pragma unroll
    for (int q = 0; q < 4; q++) {
        int fi = q * 256 + tid;
        int gfi = rowbase * 16 + fi;
        float4 v = (gfi < N_MAT * 16) ? mat4[gfi] : make_float4(0.f, 0.f, 0.f, 0.f);
        *(float4*)&m[(fi >> 4) * 68 + (fi & 15) * 4] = v;
    }
    __syncthreads();

    int cr = tid & 15, rr = tid >> 4;
    int c0 = cr * 4, r0 = rr * 4;
    float4 acc[4];
#pragma unroll
    for (int r = 0; r < 4; r++) acc[r] = make_float4(0.f, 0.f, 0.f, 0.f);
#pragma unroll
    for (int kk = 0; kk < 16; kk++) {
        float4 b0 = *(float4*)&wt[(kk * 4 + 0) * 68 + c0];
        float4 b1 = *(float4*)&wt[(kk * 4 + 1) * 68 + c0];
        float4 b2 = *(float4*)&wt[(kk * 4 + 2) * 68 + c0];
        float4 b3 = *(float4*)&wt[(kk * 4 + 3) * 68 + c0];
#pragma unroll
        for (int r = 0; r < 4; r++) {
            float4 a = *(float4*)&m[(r0 + r) * 68 + kk * 4];
            acc[r].x += a.x * b0.x + a.y * b1.x + a.z * b2.x + a.w * b3.x;
            acc[r].y += a.x * b0.y + a.y * b1.y + a.z * b2.y + a.w * b3.y;
            acc[r].z += a.x * b0.z + a.y * b1.z + a.z * b2.z + a.w * b3.z;
            acc[r].w += a.x * b0.w + a.y * b1.w + a.z * b2.w + a.w * b3.w;
        }
    }
    unsigned hmask = 0xFFFFu << ((tid & 31) & 16);
    float4 a1 = *(float4*)&ac1[c0];
    float4 as = *(float4*)&asc[c0];
    float exl = 0.f;
#pragma unroll
    for (int r = 0; r < 4; r++) {
        int row = rowbase + r0 + r;
        bool valid = row < N_MAT;
        if (valid) *(float4*)&g_h[row * 64 + c0] = acc[r];
        float dv = acc[r].x * a1.x + acc[r].y * a1.y + acc[r].z * a1.z + acc[r].w * a1.w;
        float sv = acc[r].x * as.x + acc[r].y * as.y + acc[r].z * as.z + acc[r].w * as.w;
#pragma unroll
        for (int o = 8; o; o >>= 1) {
            dv += __shfl_xor_sync(hmask, dv, o, 16);
            sv += __shfl_xor_sync(hmask, sv, o, 16);
        }
        if (cr == 0 && valid) {
            g_d[row] = dv;
            float s = sv > 0.f ? sv : 0.2f * sv;
            float ex = __expf(s);
            g_expself[row] = ex;
            exl += ex;
        }
    }
    if (cr == 0) s_ex[rr] = exl;
    __syncthreads();
    if (tid == 0) {
        float t = 0.f;
#pragma unroll
        for (int i = 0; i < 16; i++) t += s_ex[i];
        g_part_self[blockIdx.x] = t;
    }
}

// ---------------- K2: p[op] = operations[op] . b[:48] (measured-best scalar) ----
__global__ void __launch_bounds__(256) k_pops(const float* __restrict__ ops) {
    __shared__ float bs[48];
    int tid = threadIdx.x;
    if (tid < 48) bs[tid] = g_b[tid];
    __syncthreads();
    int op = blockIdx.x * 16 + (tid >> 4);
    int j = tid & 15;
    const float* r = ops + op * 48;
    float v = r[j] * bs[j] + r[16 + j] * bs[16 + j] + r[32 + j] * bs[32 + j];
#pragma unroll
    for (int o = 8; o; o >>= 1) v += __shfl_xor_sync(0xffffffffu, v, o);
    if (j == 0) g_p[op] = v;
}

// ---------------- K3: cross scores (1 edge/thread) + degree count ---------------
__global__ void __launch_bounds__(256) k_escore(const float* __restrict__ ea,
                                                const int* __restrict__ ei) {
    __shared__ float b16[16];
    __shared__ float spart[8];
    int tid = threadIdx.x;
    if (tid < 16) b16[tid] = g_b[48 + tid];
    __syncthreads();
    int e = blockIdx.x * 256 + tid;
    int src = ei[e];
    int dst = ei[N_EDGE + e];
    const float4* ea4 = (const float4*)ea;
    float s = g_d[dst] + g_p[src];
#pragma unroll
    for (int q = 0; q < 4; q++) {
        float4 v = ea4[e * 4 + q];
        s += v.x * b16[4 * q] + v.y * b16[4 * q + 1] + v.z * b16[4 * q + 2] + v.w * b16[4 * q + 3];
    }
    s = s > 0.f ? s : 0.2f * s;
    float ex = __expf(s);
    g_expcross[e] = ex;
    atomicAdd(&g_cnt[dst], 1);
    float wsum = warp_sum(ex);
    if ((tid & 31) == 0) spart[tid >> 5] = wsum;
    __syncthreads();
    if (tid == 0) {
        float t = 0.f;
#pragma unroll
        for (int i = 0; i < 8; i++) t += spart[i];
        g_part_cross[blockIdx.x] = t;
    }
}

// ---------------- scan1: block-local exclusive scan + per-block totals ----------
__global__ void k_scan1() {
    __shared__ int s[256];
    int tid = threadIdx.x;
    int i = blockIdx.x * 256 + tid;
    int v = (i < N_MAT) ? g_cnt[i] : 0;
    s[tid] = v;
    __syncthreads();
#pragma unroll
    for (int o = 1; o < 256; o <<= 1) {
        int t = (tid >= o) ? s[tid - o] : 0;
        __syncthreads();
        if (tid >= o) s[tid] += t;
        __syncthreads();
    }
    if (i < N_MAT) g_start[i] = s[tid] - v;
    if (tid == 255) g_part[blockIdx.x] = s[255];
}

// ---- scan23: every block scans the 196 partials, applies its offset; block 0
//      also computes the deterministic softmax denominator ----------------------
__global__ void k_scan23() {
    __shared__ int s[256];
    int tid = threadIdx.x;
    int bb = blockIdx.x;
    int pv = (tid < NB_SCAN) ? g_part[tid] : 0;
    s[tid] = pv;
    __syncthreads();
#pragma unroll
    for (int o = 1; o < 256; o <<= 1) {
        int t = (tid >= o) ? s[tid - o] : 0;
        __syncthreads();
        if (tid >= o) s[tid] += t;
        __syncthreads();
    }
    int off = (bb == 0) ? 0 : s[bb - 1];
    int i = bb * 256 + tid;
    if (i < N_MAT) {
        int st = g_start[i] + off;
        g_start[i] = st;
        g_cur[i] = st;
    }
    if (bb == 0) {
        __shared__ float sp[8];
        float t = 0.f;
        for (int k = tid; k < NODES_NB; k += 256) t += g_part_self[k];
        for (int k = tid; k < ESC_NB; k += 256) t += g_part_cross[k];
        t = warp_sum(t);
        if ((tid & 31) == 0) sp[tid >> 5] = t;
        __syncthreads();
        if (tid == 0) {
            float tt = 0.f;
#pragma unroll
            for (int k = 0; k < 8; k++) tt += sp[k];
            g_sum = tt;
        }
    }
}

// ---------------- fill: scatter edges into CSR order ----------------------------
__global__ void __launch_bounds__(256) k_fill(const int* __restrict__ ei) {
    int e = blockIdx.x * 256 + threadIdx.x;
    int src = ei[e];
    int dst = ei[N_EDGE + e];
    float w = g_expcross[e];
    int pos = atomicAdd(&g_cur[dst], 1);
    g_csr[pos] = make_uint4((unsigned)e, (unsigned)src, __float_as_uint(w), 0u);
}

// ---- segmented accumulate: THE CHANGE — one WARP per row. Lanes 0-15 process
//      even CSR entries, lanes 16-31 odd entries of the SAME row; partials merge
//      via shfl_xor(16). Halves the serial chain, removes cross-row divergence. -
__global__ void __launch_bounds__(256) k_accum_csr(const float* __restrict__ ops,
                                                   const float* __restrict__ ea) {
    int tid = threadIdx.x;
    int warp = tid >> 5;
    int row = blockIdx.x * 8 + warp;          // grid exact: 6250*8 = 50000
    int p = (tid >> 4) & 1;                   // group parity: even/odd entries
    int j = tid & 15;                         // component lane
    unsigned hmask = 0xFFFFu << ((tid & 31) & 16);
    int beg = g_start[row];
    int cnt = g_cnt[row];
    const float4* ea4 = (const float4*)ea;
    const float4* ops4 = (const float4*)ops;
    float4 acc = make_float4(0.f, 0.f, 0.f, 0.f);
    bool isops = (j < 12);

    for (int base = 0; base < cnt; base += 32) {
        int rem = cnt - base;
        int myidx = base + 2 * j + p;                       // this lane's entry
        uint4 ent = (myidx < cnt) ? g_csr[beg + myidx] : make_uint4(0u, 0u, 0u, 0u);
        int nbg = (rem - p + 1) >> 1;                       // entries for this group
        if (nbg > 16) nbg = 16;
        if (nbg == 16) {
#pragma unroll
            for (int i = 0; i < 16; i++) {
                unsigned eid = __shfl_sync(hmask, ent.x, i, 16);
                unsigned src = __shfl_sync(hmask, ent.y, i, 16);
                float w = __uint_as_float(__shfl_sync(hmask, ent.z, i, 16));
                float4 v = isops ? ops4[src * 12 + j] : ea4[eid * 4 + (j - 12)];
                acc.x += w * v.x; acc.y += w * v.y; acc.z += w * v.z; acc.w += w * v.w;
            }
        } else {
            for (int i = 0; i < nbg; i++) {
                unsigned eid = __shfl_sync(hmask, ent.x, i, 16);
                unsigned src = __shfl_sync(hmask, ent.y, i, 16);
                float w = __uint_as_float(__shfl_sync(hmask, ent.z, i, 16));
                float4 v = isops ? ops4[src * 12 + j] : ea4[eid * 4 + (j - 12)];
                acc.x += w * v.x; acc.y += w * v.y; acc.z += w * v.z; acc.w += w * v.w;
            }
        }
    }
    // merge even/odd partials across the two 16-lane groups
    acc.x += __shfl_xor_sync(0xffffffffu, acc.x, 16);
    acc.y += __shfl_xor_sync(0xffffffffu, acc.y, 16);
    acc.z += __shfl_xor_sync(0xffffffffu, acc.z, 16);
    acc.w += __shfl_xor_sync(0xffffffffu, acc.w, 16);
    if (p == 0) ((float4*)(g_Y + row * 64))[j] = acc;
}

// ---------------- K5: register-tiled out = elu(ns*h + s_inv * Y @ W_op^T) -------
__global__ void __launch_bounds__(256) k_final(const float* __restrict__ W_op,
                                               float* __restrict__ out) {
    __shared__ float m[64 * 68];
    __shared__ float wt[64 * 68];
    __shared__ float s_inv_sh;
    int tid = threadIdx.x;
    for (int e = tid; e < 4096; e += 256)
        wt[(e & 63) * 68 + (e >> 6)] = W_op[e];
    if (tid == 0) s_inv_sh = 1.0f / g_sum;
    int rowbase = blockIdx.x * 64;
    const float4* Y4 = (const float4*)g_Y;
#pragma unroll
    for (int q = 0; q < 4; q++) {
        int fi = q * 256 + tid;
        int gfi = rowbase * 16 + fi;
        float4 v = (gfi < N_MAT * 16) ? Y4[gfi] : make_float4(0.f, 0.f, 0.f, 0.f);
        *(float4*)&m[(fi >> 4) * 68 + (fi & 15) * 4] = v;
    }
    __syncthreads();
    float s_inv = s_inv_sh;

    int cr = tid & 15, rr = tid >> 4;
    int c0 = cr * 4, r0 = rr * 4;
    float4 acc[4];
#pragma unroll
    for (int r = 0; r < 4; r++) acc[r] = make_float4(0.f, 0.f, 0.f, 0.f);
#pragma unroll
    for (int kk = 0; kk < 16; kk++) {
        float4 b0 = *(float4*)&wt[(kk * 4 + 0) * 68 + c0];
        float4 b1 = *(float4*)&wt[(kk * 4 + 1) * 68 + c0];
        float4 b2 = *(float4*)&wt[(kk * 4 + 2) * 68 + c0];
        float4 b3 = *(float4*)&wt[(kk * 4 + 3) * 68 + c0];
#pragma unroll
        for (int r = 0; r < 4; r++) {
            float4 a = *(float4*)&m[(r0 + r) * 68 + kk * 4];
            acc[r].x += a.x * b0.x + a.y * b1.x + a.z * b2.x + a.w * b3.x;
            acc[r].y += a.x * b0.y + a.y * b1.y + a.z * b2.y + a.w * b3.y;
            acc[r].z += a.x * b0.z + a.y * b1.z + a.z * b2.z + a.w * b3.z;
            acc[r].w += a.x * b0.w + a.y * b1.w + a.z * b2.w + a.w * b3.w;
        }
    }
#pragma unroll
    for (int r = 0; r < 4; r++) {
        int row = rowbase + r0 + r;
        if (row < N_MAT) {
            float ns = g_expself[row] * s_inv;
            float4 h4 = *(const float4*)&g_h[row * 64 + c0];
            float4 o;
            o.x = ns * h4.x + s_inv * acc[r].x;
            o.y = ns * h4.y + s_inv * acc[r].y;
            o.z = ns * h4.z + s_inv * acc[r].z;
            o.w = ns * h4.w + s_inv * acc[r].w;
            o.x = o.x > 0.f ? o.x : expm1f(o.x);
            o.y = o.y > 0.f ? o.y : expm1f(o.y);
            o.z = o.z > 0.f ? o.z : expm1f(o.z);
            o.w = o.w > 0.f ? o.w : expm1f(o.w);
            *(float4*)&out[row * 64 + c0] = o;
        }
    }
}

extern "C" void kernel_launch(void* const* d_in, const int* in_sizes, int n_in,
                              void* d_out, int out_size) {
    const float* materials  = (const float*)d_in[0];
    const float* operations = (const float*)d_in[1];
    const float* edge_attr  = (const float*)d_in[2];
    const int*   edge_index = (const int*)d_in[3];
    const float* W_mat      = (const float*)d_in[4];
    const float* W_op       = (const float*)d_in[5];
    const float* a_self     = (const float*)d_in[6];
    const float* a_cross    = (const float*)d_in[7];
    float* out = (float*)d_out;

    k_nodes    <<<NODES_NB, 256>>>(materials, W_mat, a_self, a_cross, W_op);
    k_pops     <<<N_MAT / 16, 256>>>(operations);
    k_escore   <<<ESC_NB, 256>>>(edge_attr, edge_index);
    k_scan1    <<<NB_SCAN, 256>>>();
    k_scan23   <<<NB_SCAN, 256>>>();
    k_fill     <<<ESC_NB, 256>>>(edge_index);
    k_accum_csr<<<N_MAT / 8, 256>>>(operations, edge_attr);
    k_final    <<<NODES_NB, 256>>>(W_op, out);
}

// round 17
// speedup vs baseline: 1.0609x; 1.0609x over previous
#include <cuda_runtime.h>

#define N_MAT 50000
#define N_EDGE 800000
#define D 64
#define NB_SCAN 196   // ceil(N_MAT/256)
#define NODES_NB 782  // ceil(N_MAT/64)
#define ESC_NB 3125   // N_EDGE/256

// ---------------- scratch (static device memory; no allocations) ----------------
__device__ __align__(16) float g_h[N_MAT * D];
__device__ __align__(16) float g_Y[N_MAT * D];
__device__ float g_d[N_MAT];
__device__ float g_p[N_MAT];
__device__ float g_expself[N_MAT];
__device__ float g_expcross[N_EDGE];
__device__ float g_b[D];
__device__ float g_sum;
__device__ int g_cnt[N_MAT];
__device__ int g_start[N_MAT];
__device__ int g_cur[N_MAT];
__device__ int g_part[NB_SCAN];
__device__ float g_part_self[NODES_NB];
__device__ float g_part_cross[ESC_NB];
__device__ __align__(16) uint4 g_csr[N_EDGE];   // {eid, src, bits(exp), pad}

__device__ __forceinline__ float warp_sum(float v) {
#pragma unroll
    for (int o = 16; o; o >>= 1) v += __shfl_xor_sync(0xffffffffu, v, o);
    return v;
}

// ---- K1: register-tiled h = mat @ W_mat^T + d + self-score
//      + per-block cnt zeroing + block0 computes b ------------------------------
__global__ void __launch_bounds__(256) k_nodes(const float* __restrict__ mat,
                                               const float* __restrict__ W_mat,
                                               const float* __restrict__ a_self,
                                               const float* __restrict__ a_cross,
                                               const float* __restrict__ W_op) {
    __shared__ float m[64 * 68];
    __shared__ float wt[64 * 68];
    __shared__ float ac1[64], asc[64];
    __shared__ float s_ex[16];
    int tid = threadIdx.x;
    int rowbase = blockIdx.x * 64;

    if (tid < 64 && rowbase + tid < N_MAT) g_cnt[rowbase + tid] = 0;
    if (blockIdx.x == 0 && tid >= 64 && tid < 128) {
        int jj = tid - 64;
        float bb = 0.f;
#pragma unroll
        for (int c = 0; c < D; c++) bb += a_cross[D + c] * W_op[c * D + jj];
        g_b[jj] = bb;
    }

    for (int e = tid; e < 4096; e += 256)
        wt[(e & 63) * 68 + (e >> 6)] = W_mat[e];
    if (tid < 64) { ac1[tid] = a_cross[tid]; asc[tid] = a_self[tid] + a_self[64 + tid]; }
    const float4* mat4 = (const float4*)mat;
#pragma unroll
    for (int q = 0; q < 4; q++) {
        int fi = q * 256 + tid;
        int gfi = rowbase * 16 + fi;
        float4 v = (gfi < N_MAT * 16) ? mat4[gfi] : make_float4(0.f, 0.f, 0.f, 0.f);
        *(float4*)&m[(fi >> 4) * 68 + (fi & 15) * 4] = v;
    }
    __syncthreads();

    int cr = tid & 15, rr = tid >> 4;
    int c0 = cr * 4, r0 = rr * 4;
    float4 acc[4];
#pragma unroll
    for (int r = 0; r < 4; r++) acc[r] = make_float4(0.f, 0.f, 0.f, 0.f);
#pragma unroll
    for (int kk = 0; kk < 16; kk++) {
        float4 b0 = *(float4*)&wt[(kk * 4 + 0) * 68 + c0];
        float4 b1 = *(float4*)&wt[(kk * 4 + 1) * 68 + c0];
        float4 b2 = *(float4*)&wt[(kk * 4 + 2) * 68 + c0];
        float4 b3 = *(float4*)&wt[(kk * 4 + 3) * 68 + c0];
#pragma unroll
        for (int r = 0; r < 4; r++) {
            float4 a = *(float4*)&m[(r0 + r) * 68 + kk * 4];
            acc[r].x += a.x * b0.x + a.y * b1.x + a.z * b2.x + a.w * b3.x;
            acc[r].y += a.x * b0.y + a.y * b1.y + a.z * b2.y + a.w * b3.y;
            acc[r].z += a.x * b0.z + a.y * b1.z + a.z * b2.z + a.w * b3.z;
            acc[r].w += a.x * b0.w + a.y * b1.w + a.z * b2.w + a.w * b3.w;
        }
    }
    unsigned hmask = 0xFFFFu << ((tid & 31) & 16);
    float4 a1 = *(float4*)&ac1[c0];
    float4 as = *(float4*)&asc[c0];
    float exl = 0.f;
#pragma unroll
    for (int r = 0; r < 4; r++) {
        int row = rowbase + r0 + r;
        bool valid = row < N_MAT;
        if (valid) *(float4*)&g_h[row * 64 + c0] = acc[r];
        float dv = acc[r].x * a1.x + acc[r].y * a1.y + acc[r].z * a1.z + acc[r].w * a1.w;
        float sv = acc[r].x * as.x + acc[r].y * as.y + acc[r].z * as.z + acc[r].w * as.w;
#pragma unroll
        for (int o = 8; o; o >>= 1) {
            dv += __shfl_xor_sync(hmask, dv, o, 16);
            sv += __shfl_xor_sync(hmask, sv, o, 16);
        }
        if (cr == 0 && valid) {
            g_d[row] = dv;
            float s = sv > 0.f ? sv : 0.2f * sv;
            float ex = __expf(s);
            g_expself[row] = ex;
            exl += ex;
        }
    }
    if (cr == 0) s_ex[rr] = exl;
    __syncthreads();
    if (tid == 0) {
        float t = 0.f;
#pragma unroll
        for (int i = 0; i < 16; i++) t += s_ex[i];
        g_part_self[blockIdx.x] = t;
    }
}

// ---------------- K2: p[op] = operations[op] . b[:48] (measured-best scalar) ----
__global__ void __launch_bounds__(256) k_pops(const float* __restrict__ ops) {
    __shared__ float bs[48];
    int tid = threadIdx.x;
    if (tid < 48) bs[tid] = g_b[tid];
    __syncthreads();
    int op = blockIdx.x * 16 + (tid >> 4);
    int j = tid & 15;
    const float* r = ops + op * 48;
    float v = r[j] * bs[j] + r[16 + j] * bs[16 + j] + r[32 + j] * bs[32 + j];
#pragma unroll
    for (int o = 8; o; o >>= 1) v += __shfl_xor_sync(0xffffffffu, v, o);
    if (j == 0) g_p[op] = v;
}

// ---------------- K3: cross scores (1 edge/thread) + degree count ---------------
__global__ void __launch_bounds__(256) k_escore(const float* __restrict__ ea,
                                                const int* __restrict__ ei) {
    __shared__ float b16[16];
    __shared__ float spart[8];
    int tid = threadIdx.x;
    if (tid < 16) b16[tid] = g_b[48 + tid];
    __syncthreads();
    int e = blockIdx.x * 256 + tid;
    int src = ei[e];
    int dst = ei[N_EDGE + e];
    const float4* ea4 = (const float4*)ea;
    float s = g_d[dst] + g_p[src];
#pragma unroll
    for (int q = 0; q < 4; q++) {
        float4 v = ea4[e * 4 + q];
        s += v.x * b16[4 * q] + v.y * b16[4 * q + 1] + v.z * b16[4 * q + 2] + v.w * b16[4 * q + 3];
    }
    s = s > 0.f ? s : 0.2f * s;
    float ex = __expf(s);
    g_expcross[e] = ex;
    atomicAdd(&g_cnt[dst], 1);
    float wsum = warp_sum(ex);
    if ((tid & 31) == 0) spart[tid >> 5] = wsum;
    __syncthreads();
    if (tid == 0) {
        float t = 0.f;
#pragma unroll
        for (int i = 0; i < 8; i++) t += spart[i];
        g_part_cross[blockIdx.x] = t;
    }
}

// ---------------- scan1: block-local exclusive scan + per-block totals ----------
__global__ void k_scan1() {
    __shared__ int s[256];
    int tid = threadIdx.x;
    int i = blockIdx.x * 256 + tid;
    int v = (i < N_MAT) ? g_cnt[i] : 0;
    s[tid] = v;
    __syncthreads();
#pragma unroll
    for (int o = 1; o < 256; o <<= 1) {
        int t = (tid >= o) ? s[tid - o] : 0;
        __syncthreads();
        if (tid >= o) s[tid] += t;
        __syncthreads();
    }
    if (i < N_MAT) g_start[i] = s[tid] - v;
    if (tid == 255) g_part[blockIdx.x] = s[255];
}

// ---- scan23: every block scans the 196 partials, applies its offset; block 0
//      also computes the deterministic softmax denominator ----------------------
__global__ void k_scan23() {
    __shared__ int s[256];
    int tid = threadIdx.x;
    int bb = blockIdx.x;
    int pv = (tid < NB_SCAN) ? g_part[tid] : 0;
    s[tid] = pv;
    __syncthreads();
#pragma unroll
    for (int o = 1; o < 256; o <<= 1) {
        int t = (tid >= o) ? s[tid - o] : 0;
        __syncthreads();
        if (tid >= o) s[tid] += t;
        __syncthreads();
    }
    int off = (bb == 0) ? 0 : s[bb - 1];
    int i = bb * 256 + tid;
    if (i < N_MAT) {
        int st = g_start[i] + off;
        g_start[i] = st;
        g_cur[i] = st;
    }
    if (bb == 0) {
        __shared__ float sp[8];
        float t = 0.f;
        for (int k = tid; k < NODES_NB; k += 256) t += g_part_self[k];
        for (int k = tid; k < ESC_NB; k += 256) t += g_part_cross[k];
        t = warp_sum(t);
        if ((tid & 31) == 0) sp[tid >> 5] = t;
        __syncthreads();
        if (tid == 0) {
            float tt = 0.f;
#pragma unroll
            for (int k = 0; k < 8; k++) tt += sp[k];
            g_sum = tt;
        }
    }
}

// ---------------- fill: scatter edges into CSR order ----------------------------
__global__ void __launch_bounds__(256) k_fill(const int* __restrict__ ei) {
    int e = blockIdx.x * 256 + threadIdx.x;
    int src = ei[e];
    int dst = ei[N_EDGE + e];
    float w = g_expcross[e];
    int pos = atomicAdd(&g_cur[dst], 1);
    g_csr[pos] = make_uint4((unsigned)e, (unsigned)src, __float_as_uint(w), 0u);
}

// -------- segmented accumulate (measured-best shuffle form, unchanged) ----------
__global__ void __launch_bounds__(256) k_accum_csr(const float* __restrict__ ops,
                                                   const float* __restrict__ ea) {
    int tid = threadIdx.x;
    int row = blockIdx.x * 16 + (tid >> 4);
    int j = tid & 15;
    unsigned hmask = 0xFFFFu << ((tid & 31) & 16);
    int beg = g_start[row];
    int cnt = g_cnt[row];
    const float4* ea4 = (const float4*)ea;
    const float4* ops4 = (const float4*)ops;
    float4 acc = make_float4(0.f, 0.f, 0.f, 0.f);
    for (int base = 0; base < cnt; base += 16) {
        int rem = cnt - base;
        int nb = rem < 16 ? rem : 16;
        uint4 ent = (j < nb) ? g_csr[beg + base + j] : make_uint4(0u, 0u, 0u, 0u);
#pragma unroll 8
        for (int i = 0; i < nb; i++) {
            unsigned eid = __shfl_sync(hmask, ent.x, i, 16);
            unsigned src = __shfl_sync(hmask, ent.y, i, 16);
            float w = __uint_as_float(__shfl_sync(hmask, ent.z, i, 16));
            float4 v = (j < 12) ? ops4[src * 12 + j] : ea4[eid * 4 + (j - 12)];
            acc.x += w * v.x; acc.y += w * v.y; acc.z += w * v.z; acc.w += w * v.w;
        }
    }
    ((float4*)(g_Y + row * 64))[j] = acc;
}

// ---------------- K5: register-tiled out = elu(ns*h + s_inv * Y @ W_op^T) -------
__global__ void __launch_bounds__(256) k_final(const float* __restrict__ W_op,
                                               float* __restrict__ out) {
    __shared__ float m[64 * 68];
    __shared__ float wt[64 * 68];
    __shared__ float s_inv_sh;
    int tid = threadIdx.x;
    for (int e = tid; e < 4096; e += 256)
        wt[(e & 63) * 68 + (e >> 6)] = W_op[e];
    if (tid == 0) s_inv_sh = 1.0f / g_sum;
    int rowbase = blockIdx.x * 64;
    const float4* Y4 = (const float4*)g_Y;
#pragma unroll
    for (int q = 0; q < 4; q++) {
        int fi = q * 256 + tid;
        int gfi = rowbase * 16 + fi;
        float4 v = (gfi < N_MAT * 16) ? Y4[gfi] : make_float4(0.f, 0.f, 0.f, 0.f);
        *(float4*)&m[(fi >> 4) * 68 + (fi & 15) * 4] = v;
    }
    __syncthreads();
    float s_inv = s_inv_sh;

    int cr = tid & 15, rr = tid >> 4;
    int c0 = cr * 4, r0 = rr * 4;
    float4 acc[4];
#pragma unroll
    for (int r = 0; r < 4; r++) acc[r] = make_float4(0.f, 0.f, 0.f, 0.f);
#pragma unroll
    for (int kk = 0; kk < 16; kk++) {
        float4 b0 = *(float4*)&wt[(kk * 4 + 0) * 68 + c0];
        float4 b1 = *(float4*)&wt[(kk * 4 + 1) * 68 + c0];
        float4 b2 = *(float4*)&wt[(kk * 4 + 2) * 68 + c0];
        float4 b3 = *(float4*)&wt[(kk * 4 + 3) * 68 + c0];
#pragma unroll
        for (int r = 0; r < 4; r++) {
            float4 a = *(float4*)&m[(r0 + r) * 68 + kk * 4];
            acc[r].x += a.x * b0.x + a.y * b1.x + a.z * b2.x + a.w * b3.x;
            acc[r].y += a.x * b0.y + a.y * b1.y + a.z * b2.y + a.w * b3.y;
            acc[r].z += a.x * b0.z + a.y * b1.z + a.z * b2.z + a.w * b3.z;
            acc[r].w += a.x * b0.w + a.y * b1.w + a.z * b2.w + a.w * b3.w;
        }
    }
#pragma unroll
    for (int r = 0; r < 4; r++) {
        int row = rowbase + r0 + r;
        if (row < N_MAT) {
            float ns = g_expself[row] * s_inv;
            float4 h4 = *(const float4*)&g_h[row * 64 + c0];
            float4 o;
            o.x = ns * h4.x + s_inv * acc[r].x;
            o.y = ns * h4.y + s_inv * acc[r].y;
            o.z = ns * h4.z + s_inv * acc[r].z;
            o.w = ns * h4.w + s_inv * acc[r].w;
            o.x = o.x > 0.f ? o.x : expm1f(o.x);
            o.y = o.y > 0.f ? o.y : expm1f(o.y);
            o.z = o.z > 0.f ? o.z : expm1f(o.z);
            o.w = o.w > 0.f ? o.w : expm1f(o.w);
            *(float4*)&out[row * 64 + c0] = o;
        }
    }
}

extern "C" void kernel_launch(void* const* d_in, const int* in_sizes, int n_in,
                              void* d_out, int out_size) {
    const float* materials  = (const float*)d_in[0];
    const float* operations = (const float*)d_in[1];
    const float* edge_attr  = (const float*)d_in[2];
    const int*   edge_index = (const int*)d_in[3];
    const float* W_mat      = (const float*)d_in[4];
    const float* W_op       = (const float*)d_in[5];
    const float* a_self     = (const float*)d_in[6];
    const float* a_cross    = (const float*)d_in[7];
    float* out = (float*)d_out;

    k_nodes    <<<NODES_NB, 256>>>(materials, W_mat, a_self, a_cross, W_op);
    k_pops     <<<N_MAT / 16, 256>>>(operations);
    k_escore   <<<ESC_NB, 256>>>(edge_attr, edge_index);
    k_scan1    <<<NB_SCAN, 256>>>();
    k_scan23   <<<NB_SCAN, 256>>>();
    k_fill     <<<ESC_NB, 256>>>(edge_index);
    k_accum_csr<<<N_MAT / 16, 256>>>(operations, edge_attr);
    k_final    <<<NODES_NB, 256>>>(W_op, out);
}